// round 15
// baseline (speedup 1.0000x reference)
#include <cuda_runtime.h>
#include <cuda_bf16.h>
#include <cuda_fp16.h>
#include <cstdint>

#define NN 100000
#define EE 1600000
#define F0 256
#define FH 128
#define FC 40

// ---------------- static device scratch ----------------
__device__ float  g_h[(size_t)NN * FH];    // layer-2 gemm output (fp32, read by agg2)
__device__ __half g_hh[(size_t)NN * FH];   // layer-1 gemm output (fp16, read by agg1)
__device__ int   g_deg[NN];
__device__ float g_dinv[NN];
__device__ int   g_rowptr[NN + 1];
__device__ int   g_col[EE];
__device__ int   g_slot[EE];
__device__ int   g_is64;
__device__ __nv_bfloat16 g_Ahi[(size_t)NN * FH];   // agg output hi (GEMM A operand)
__device__ __nv_bfloat16 g_Alo[(size_t)NN * FH];
__device__ __nv_bfloat16 g_W1thi[FH * F0], g_W1tlo[FH * F0];   // [128][256] K-major
__device__ __nv_bfloat16 g_W2thi[FH * FH], g_W2tlo[FH * FH];   // [128][128] K-major
__device__ __nv_bfloat16 g_Wcthi[64 * FH], g_Wctlo[64 * FH];   // [64(pad40)][128] K-major

// ---------------- helpers ----------------
__device__ __forceinline__ uint32_t smem_u32(const void* p) {
    uint32_t a;
    asm("{ .reg .u64 t; cvta.to.shared.u64 t, %1; cvt.u32.u64 %0, t; }" : "=r"(a) : "l"(p));
    return a;
}
#define LDSM_X4(r0, r1, r2, r3, addr) \
    asm volatile("ldmatrix.sync.aligned.m8n8.x4.shared.b16 {%0,%1,%2,%3}, [%4];" \
                 : "=r"(r0), "=r"(r1), "=r"(r2), "=r"(r3) : "r"(addr))
#define MMA16816(d, a, b) \
    asm volatile("mma.sync.aligned.m16n8k16.row.col.f32.bf16.bf16.f32 " \
                 "{%0,%1,%2,%3}, {%4,%5,%6,%7}, {%8,%9}, {%0,%1,%2,%3};" \
                 : "+f"((d)[0]), "+f"((d)[1]), "+f"((d)[2]), "+f"((d)[3]) \
                 : "r"((a)[0]), "r"((a)[1]), "r"((a)[2]), "r"((a)[3]), \
                   "r"((b)[0]), "r"((b)[1]))
#define CP_ASYNC16(dst, src, sz) \
    asm volatile("cp.async.cg.shared.global [%0], [%1], 16, %2;" \
                 :: "r"(dst), "l"(src), "r"(sz) : "memory")
#define CP_COMMIT asm volatile("cp.async.commit_group;" ::: "memory")
#define CP_WAIT(n) asm volatile("cp.async.wait_group %0;" :: "n"(n) : "memory")

__device__ __forceinline__ int load_edge(const void* ei, long long idx, int is64) {
    if (is64) return (int)((const long long*)ei)[idx];
    return ((const int*)ei)[idx];
}
__device__ __forceinline__ void split1(float f, __nv_bfloat16& hi, __nv_bfloat16& lo) {
    hi = __float2bfloat16(f);
    lo = __float2bfloat16(f - __bfloat162float(hi));
}

#define SKEW 40
#define TILE_B (128 * SKEW * 2)     // 10240 bytes
#define STAGE_B (4 * TILE_B)
#define GSM_TOTAL (2 * STAGE_B)     // 81920

// ============ K0: detect ∥ split W1/W2/Wc (deg zeroed by prev replay's clf) ==
__global__ void k0_prep(const int* __restrict__ ei32, int total_words,
                        const float* __restrict__ W1, const float* __restrict__ W2,
                        const float* __restrict__ Wc, int bW1, int bW2) {
    int b = blockIdx.x, tid = threadIdx.x;
    if (b == 0) {
        __shared__ int acc;
        if (tid == 0) acc = 0;
        __syncthreads();
        int v = 0;
        int lim = min(total_words, 8192);
        for (int i = 1 + 2 * tid; i < lim; i += 2 * blockDim.x) v |= ei32[i];
        if (v) atomicOr(&acc, 1);
        __syncthreads();
        if (tid == 0) g_is64 = (acc == 0) ? 1 : 0;
    } else if (b < 1 + bW1) {
        int i = (b - 1) * 256 + tid;
        if (i < F0 * FH) {
            int k = i / FH, nidx = i % FH;
            __nv_bfloat16 hi, lo;
            split1(W1[i], hi, lo);
            g_W1thi[nidx * F0 + k] = hi;
            g_W1tlo[nidx * F0 + k] = lo;
        }
    } else if (b < 1 + bW1 + bW2) {
        int i = (b - 1 - bW1) * 256 + tid;
        if (i < FH * FH) {
            int k = i / FH, nidx = i % FH;
            __nv_bfloat16 hi, lo;
            split1(W2[i], hi, lo);
            g_W2thi[nidx * FH + k] = hi;
            g_W2tlo[nidx * FH + k] = lo;
        }
    } else {
        int i = (b - 1 - bW1 - bW2) * 256 + tid;
        if (i < 64 * FH) {
            int nidx = i / FH, k = i % FH;
            float f = (nidx < FC) ? Wc[k * FC + nidx] : 0.f;
            __nv_bfloat16 hi, lo;
            split1(f, hi, lo);
            g_Wcthi[nidx * FH + k] = hi;
            g_Wctlo[nidx * FH + k] = lo;
        }
    }
}

// ============ scan: exclusive prefix of g_deg -> g_rowptr (1 block) ==========
__global__ void scan_kernel(int n) {
    __shared__ int sh[1024];
    int tid = threadIdx.x;
    int chunk = (n + 1023) >> 10;
    int start = tid * chunk, end = min(start + chunk, n);
    int sum = 0;
    for (int i = start; i < end; i++) sum += g_deg[i];
    sh[tid] = sum;
    __syncthreads();
    for (int off = 1; off < 1024; off <<= 1) {
        int v = 0;
        if (tid >= off) v = sh[tid - off];
        __syncthreads();
        sh[tid] += v;
        __syncthreads();
    }
    int run = sh[tid] - sum;
    for (int i = start; i < end; i++) { g_rowptr[i] = run; run += g_deg[i]; }
    if (end == n) g_rowptr[n] = run;
}

// ============ shared MMA compute for one 32-wide K chunk =====================
__device__ __forceinline__ void compute_chunk(
    uint32_t aAhi, uint32_t aAlo, uint32_t aBhi, uint32_t aBlo,
    int warp_m, int warp_n, int lane, float acc[2][8][4])
{
    #pragma unroll
    for (int kk = 0; kk < 32; kk += 16) {
        uint32_t ah[2][4], al[2][4];
        #pragma unroll
        for (int mi = 0; mi < 2; mi++) {
            int row = warp_m * 32 + mi * 16 + (lane & 15);
            int col = kk + (lane >> 4) * 8;
            uint32_t off = (uint32_t)(row * SKEW + col) * 2;
            LDSM_X4(ah[mi][0], ah[mi][1], ah[mi][2], ah[mi][3], aAhi + off);
            LDSM_X4(al[mi][0], al[mi][1], al[mi][2], al[mi][3], aAlo + off);
        }
        uint32_t b[8][2];
        int g = lane >> 3;
        #pragma unroll
        for (int p = 0; p < 4; p++) {
            int nrow = warp_n * 64 + p * 16 + (g >> 1) * 8 + (lane & 7);
            int col = kk + (g & 1) * 8;
            uint32_t off = (uint32_t)(nrow * SKEW + col) * 2;
            uint32_t r0, r1, r2, r3;
            LDSM_X4(r0, r1, r2, r3, aBhi + off);
            b[p * 2][0] = r0; b[p * 2][1] = r1;
            b[p * 2 + 1][0] = r2; b[p * 2 + 1][1] = r3;
        }
        #pragma unroll
        for (int mi = 0; mi < 2; mi++)
            #pragma unroll
            for (int ni = 0; ni < 8; ni++) {
                MMA16816(acc[mi][ni], ah[mi], b[ni]);
                MMA16816(acc[mi][ni], al[mi], b[ni]);
            }
        #pragma unroll
        for (int p = 0; p < 4; p++) {
            int nrow = warp_n * 64 + p * 16 + (g >> 1) * 8 + (lane & 7);
            int col = kk + (g & 1) * 8;
            uint32_t off = (uint32_t)(nrow * SKEW + col) * 2;
            uint32_t r0, r1, r2, r3;
            LDSM_X4(r0, r1, r2, r3, aBlo + off);
            b[p * 2][0] = r0; b[p * 2][1] = r1;
            b[p * 2 + 1][0] = r2; b[p * 2 + 1][1] = r3;
        }
        #pragma unroll
        for (int mi = 0; mi < 2; mi++)
            #pragma unroll
            for (int ni = 0; ni < 8; ni++)
                MMA16816(acc[mi][ni], ah[mi], b[ni]);
    }
}

// fp32 epilogue -> g_h (gemm2)
__device__ __forceinline__ void gemm_epilogue_f32(float acc[2][8][4], int m0,
                                                  int warp_m, int warp_n, int lane, int M) {
    int gid = lane >> 2, tig = lane & 3;
    #pragma unroll
    for (int mi = 0; mi < 2; mi++) {
        #pragma unroll
        for (int ni = 0; ni < 8; ni++) {
            int col = warp_n * 64 + ni * 8 + tig * 2;
            int r0 = m0 + warp_m * 32 + mi * 16 + gid;
            if (r0 < M)
                *(float2*)(g_h + (size_t)r0 * 128 + col) =
                    make_float2(acc[mi][ni][0], acc[mi][ni][1]);
            int r1 = r0 + 8;
            if (r1 < M)
                *(float2*)(g_h + (size_t)r1 * 128 + col) =
                    make_float2(acc[mi][ni][2], acc[mi][ni][3]);
        }
    }
}

// fp16 epilogue -> g_hh (gemm1)
__device__ __forceinline__ void gemm_epilogue_f16(float acc[2][8][4], int m0,
                                                  int warp_m, int warp_n, int lane, int M) {
    int gid = lane >> 2, tig = lane & 3;
    #pragma unroll
    for (int mi = 0; mi < 2; mi++) {
        #pragma unroll
        for (int ni = 0; ni < 8; ni++) {
            int col = warp_n * 64 + ni * 8 + tig * 2;
            int r0 = m0 + warp_m * 32 + mi * 16 + gid;
            if (r0 < M)
                *(__half2*)(g_hh + (size_t)r0 * 128 + col) =
                    __floats2half2_rn(acc[mi][ni][0], acc[mi][ni][1]);
            int r1 = r0 + 8;
            if (r1 < M)
                *(__half2*)(g_hh + (size_t)r1 * 128 + col) =
                    __floats2half2_rn(acc[mi][ni][2], acc[mi][ni][3]);
        }
    }
}

// ============ GEMM-1: reads x fp32 directly, splits on the fly ===============
__device__ void mma_gemm1_dev(char* smem, int bidx, const float* __restrict__ x, int M) {
    uint32_t sb = smem_u32(smem);
    int tid = threadIdx.x, wid = tid >> 5, lane = tid & 31;
    int m0 = bidx * 128;
    int warp_m = wid & 3, warp_n = wid >> 2;
    const int K = F0, nch = K >> 5;   // 8

    float acc[2][8][4] = {};
    float4 f[4];

    #define L1_LOADB(c) do { \
        uint32_t base = sb + 2 * TILE_B + ((c) & 1) * (2 * TILE_B); \
        _Pragma("unroll") \
        for (int it = 0; it < 2; it++) { \
            int id = it * 256 + tid; \
            int row = id >> 2, seg = id & 3; \
            uint32_t soff = (uint32_t)(row * SKEW + seg * 8) * 2; \
            CP_ASYNC16(base + soff,          g_W1thi + (size_t)row * K + ((c) << 5) + seg * 8, 16); \
            CP_ASYNC16(base + TILE_B + soff, g_W1tlo + (size_t)row * K + ((c) << 5) + seg * 8, 16); \
        } \
        CP_COMMIT; \
    } while (0)
    #define L1_LOADA(c) do { \
        _Pragma("unroll") \
        for (int it = 0; it < 4; it++) { \
            int id = it * 256 + tid; \
            int row = id >> 3, seg = id & 7; \
            int gr = m0 + row; \
            f[it] = (gr < M) ? *(const float4*)(x + (size_t)gr * K + ((c) << 5) + seg * 4) \
                             : make_float4(0.f, 0.f, 0.f, 0.f); \
        } \
    } while (0)

    L1_LOADB(0);
    L1_LOADA(0);

    for (int c = 0; c < nch; c++) {
        __syncthreads();   // all prior reads of A smem & B[(c+1)&1] complete
        if (c + 1 < nch) L1_LOADB(c + 1);
        #pragma unroll
        for (int it = 0; it < 4; it++) {
            int id = it * 256 + tid;
            int row = id >> 3, seg = id & 7;
            __nv_bfloat16 h0, h1, h2, h3, l0, l1, l2, l3;
            split1(f[it].x, h0, l0); split1(f[it].y, h1, l1);
            split1(f[it].z, h2, l2); split1(f[it].w, h3, l3);
            __nv_bfloat162 hp0; hp0.x = h0; hp0.y = h1;
            __nv_bfloat162 hp1; hp1.x = h2; hp1.y = h3;
            __nv_bfloat162 lp0; lp0.x = l0; lp0.y = l1;
            __nv_bfloat162 lp1; lp1.x = l2; lp1.y = l3;
            uint32_t soff = (uint32_t)(row * SKEW + seg * 4) * 2;
            *(uint2*)(smem + soff) = make_uint2(*(uint32_t*)&hp0, *(uint32_t*)&hp1);
            *(uint2*)(smem + TILE_B + soff) = make_uint2(*(uint32_t*)&lp0, *(uint32_t*)&lp1);
        }
        if (c + 1 < nch) { L1_LOADA(c + 1); CP_WAIT(1); }
        else             { CP_WAIT(0); }
        __syncthreads();

        uint32_t aBhi = sb + 2 * TILE_B + (c & 1) * (2 * TILE_B);
        compute_chunk(sb, sb + TILE_B, aBhi, aBhi + TILE_B, warp_m, warp_n, lane, acc);
    }
    gemm_epilogue_f16(acc, m0, warp_m, warp_n, lane, M);
    #undef L1_LOADB
    #undef L1_LOADA
}

// ============ K2: GEMM-1 ∥ degree histogram ==================================
__global__ void __launch_bounds__(256, 2) k2_gemm1_deg(
    const float* __restrict__ x, const void* __restrict__ ei, int M, int E, int gemmB) {
    extern __shared__ char smem[];
    if (blockIdx.x < gemmB) {
        mma_gemm1_dev(smem, blockIdx.x, x, M);
    } else {
        int is64 = g_is64;
        int base = ((blockIdx.x - gemmB) * 256 + threadIdx.x) * 4;
        #pragma unroll
        for (int j = 0; j < 4; j++) {
            int i = base + j;
            if (i >= E) break;
            int d = load_edge(ei, (long long)E + i, is64);
            if ((unsigned)d < (unsigned)NN)
                g_slot[i] = atomicAdd(&g_deg[d], 1);
        }
    }
}

// ============ K3: scatter (col only) ∥ dinv ==================================
__global__ void k3_scatter_dinv(const void* __restrict__ ei, int E, int n, int scatB) {
    if (blockIdx.x < scatB) {
        int is64 = g_is64;
        int base = (blockIdx.x * 256 + threadIdx.x) * 8;
        #pragma unroll
        for (int j = 0; j < 8; j++) {
            int i = base + j;
            if (i >= E) break;
            int s = load_edge(ei, i, is64);
            int d = load_edge(ei, (long long)E + i, is64);
            if ((unsigned)s >= (unsigned)NN || (unsigned)d >= (unsigned)NN) continue;
            g_col[g_rowptr[d] + g_slot[i]] = s;
        }
    } else {
        int i = (blockIdx.x - scatB) * 256 + threadIdx.x;
        if (i < n) g_dinv[i] = rsqrtf((float)g_deg[i] + 1.0f);
    }
}

// ---------------- aggregation: warp per node, 4-way ILP, bf16 hi/lo out ------
// useHalf=1: gather fp16 g_hh (layer-1);  useHalf=0: gather fp32 g_h (layer-2)
__global__ void agg_kernel(const float* __restrict__ bias, int n, int useHalf) {
    int warp = (blockIdx.x * blockDim.x + threadIdx.x) >> 5;
    if (warp >= n) return;
    int lane = threadIdx.x & 31;
    int beg = g_rowptr[warp], end = g_rowptr[warp + 1];
    const float4* hv = (const float4*)g_h;
    const uint2* hh = (const uint2*)g_hh;   // 4 halves per lane-slot

    float4 a0 = make_float4(0.f, 0.f, 0.f, 0.f), a1 = a0, a2 = a0, a3 = a0;
    int e = beg;
    if (useHalf) {
        for (; e + 4 <= end; e += 4) {
            int s0 = g_col[e],     s1 = g_col[e + 1];
            int s2 = g_col[e + 2], s3 = g_col[e + 3];
            float w0 = g_dinv[s0], w1 = g_dinv[s1];
            float w2 = g_dinv[s2], w3 = g_dinv[s3];
            uint2 r0 = hh[(size_t)s0 * 32 + lane];
            uint2 r1 = hh[(size_t)s1 * 32 + lane];
            uint2 r2 = hh[(size_t)s2 * 32 + lane];
            uint2 r3 = hh[(size_t)s3 * 32 + lane];
            float2 p0 = __half22float2(*(__half2*)&r0.x), q0 = __half22float2(*(__half2*)&r0.y);
            float2 p1 = __half22float2(*(__half2*)&r1.x), q1 = __half22float2(*(__half2*)&r1.y);
            float2 p2 = __half22float2(*(__half2*)&r2.x), q2 = __half22float2(*(__half2*)&r2.y);
            float2 p3 = __half22float2(*(__half2*)&r3.x), q3 = __half22float2(*(__half2*)&r3.y);
            a0.x += w0 * p0.x; a0.y += w0 * p0.y; a0.z += w0 * q0.x; a0.w += w0 * q0.y;
            a1.x += w1 * p1.x; a1.y += w1 * p1.y; a1.z += w1 * q1.x; a1.w += w1 * q1.y;
            a2.x += w2 * p2.x; a2.y += w2 * p2.y; a2.z += w2 * q2.x; a2.w += w2 * q2.y;
            a3.x += w3 * p3.x; a3.y += w3 * p3.y; a3.z += w3 * q3.x; a3.w += w3 * q3.y;
        }
        for (; e < end; e++) {
            int s0 = g_col[e];
            float w0 = g_dinv[s0];
            uint2 r0 = hh[(size_t)s0 * 32 + lane];
            float2 p0 = __half22float2(*(__half2*)&r0.x), q0 = __half22float2(*(__half2*)&r0.y);
            a0.x += w0 * p0.x; a0.y += w0 * p0.y; a0.z += w0 * q0.x; a0.w += w0 * q0.y;
        }
    } else {
        for (; e + 4 <= end; e += 4) {
            int s0 = g_col[e],     s1 = g_col[e + 1];
            int s2 = g_col[e + 2], s3 = g_col[e + 3];
            float w0 = g_dinv[s0], w1 = g_dinv[s1];
            float w2 = g_dinv[s2], w3 = g_dinv[s3];
            float4 v0 = hv[(size_t)s0 * 32 + lane];
            float4 v1 = hv[(size_t)s1 * 32 + lane];
            float4 v2 = hv[(size_t)s2 * 32 + lane];
            float4 v3 = hv[(size_t)s3 * 32 + lane];
            a0.x += w0 * v0.x; a0.y += w0 * v0.y; a0.z += w0 * v0.z; a0.w += w0 * v0.w;
            a1.x += w1 * v1.x; a1.y += w1 * v1.y; a1.z += w1 * v1.z; a1.w += w1 * v1.w;
            a2.x += w2 * v2.x; a2.y += w2 * v2.y; a2.z += w2 * v2.z; a2.w += w2 * v2.w;
            a3.x += w3 * v3.x; a3.y += w3 * v3.y; a3.z += w3 * v3.z; a3.w += w3 * v3.w;
        }
        for (; e < end; e++) {
            int s0 = g_col[e];
            float w0 = g_dinv[s0];
            float4 v0 = hv[(size_t)s0 * 32 + lane];
            a0.x += w0 * v0.x; a0.y += w0 * v0.y; a0.z += w0 * v0.z; a0.w += w0 * v0.w;
        }
    }
    a0.x += a1.x + a2.x + a3.x;
    a0.y += a1.y + a2.y + a3.y;
    a0.z += a1.z + a2.z + a3.z;
    a0.w += a1.w + a2.w + a3.w;

    float di = g_dinv[warp], di2 = di * di;
    float4 hs;
    if (useHalf) {
        uint2 rs = hh[(size_t)warp * 32 + lane];
        float2 ps = __half22float2(*(__half2*)&rs.x), qs = __half22float2(*(__half2*)&rs.y);
        hs = make_float4(ps.x, ps.y, qs.x, qs.y);
    } else {
        hs = hv[(size_t)warp * 32 + lane];
    }
    float4 bb = ((const float4*)bias)[lane];
    float4 r;
    r.x = fmaxf(di * a0.x + di2 * hs.x + bb.x, 0.f);
    r.y = fmaxf(di * a0.y + di2 * hs.y + bb.y, 0.f);
    r.z = fmaxf(di * a0.z + di2 * hs.z + bb.z, 0.f);
    r.w = fmaxf(di * a0.w + di2 * hs.w + bb.w, 0.f);

    __nv_bfloat16 h0, h1, h2, h3, l0, l1, l2, l3;
    split1(r.x, h0, l0); split1(r.y, h1, l1);
    split1(r.z, h2, l2); split1(r.w, h3, l3);
    __nv_bfloat162 hp0; hp0.x = h0; hp0.y = h1;
    __nv_bfloat162 hp1; hp1.x = h2; hp1.y = h3;
    __nv_bfloat162 lp0; lp0.x = l0; lp0.y = l1;
    __nv_bfloat162 lp1; lp1.x = l2; lp1.y = l3;
    size_t idx2 = (size_t)warp * 64 + lane * 2;
    ((__nv_bfloat162*)g_Ahi)[idx2] = hp0;
    ((__nv_bfloat162*)g_Ahi)[idx2 + 1] = hp1;
    ((__nv_bfloat162*)g_Alo)[idx2] = lp0;
    ((__nv_bfloat162*)g_Alo)[idx2 + 1] = lp1;
}

// ============ GEMM-2: bf16 A from g_Ahi/g_Alo (cp.async 2-stage) =============
__device__ __forceinline__ void gemm2_load_stage(uint32_t sbase, int m0, int kc, int M) {
    int tid = threadIdx.x;
    #pragma unroll
    for (int it = 0; it < 2; it++) {
        int id = it * 256 + tid;
        int row = id >> 2, seg = id & 3;
        uint32_t soff = (uint32_t)(row * SKEW + seg * 8) * 2;
        int gr = m0 + row;
        int ok = (gr < M) ? 16 : 0;
        size_t grc = (gr < M) ? (size_t)gr : 0;
        CP_ASYNC16(sbase + soff,              g_Ahi + grc * FH + kc + seg * 8, ok);
        CP_ASYNC16(sbase + TILE_B + soff,     g_Alo + grc * FH + kc + seg * 8, ok);
        CP_ASYNC16(sbase + 2 * TILE_B + soff, g_W2thi + (size_t)row * FH + kc + seg * 8, 16);
        CP_ASYNC16(sbase + 3 * TILE_B + soff, g_W2tlo + (size_t)row * FH + kc + seg * 8, 16);
    }
}

__global__ void __launch_bounds__(256, 2) mma_gemm2(int M) {
    extern __shared__ char smem[];
    uint32_t sb = smem_u32(smem);
    int tid = threadIdx.x, wid = tid >> 5, lane = tid & 31;
    int m0 = blockIdx.x * 128;
    int warp_m = wid & 3, warp_n = wid >> 2;

    float acc[2][8][4] = {};
    const int nch = FH >> 5;   // 4

    gemm2_load_stage(sb, m0, 0, M);
    CP_COMMIT;
    for (int c = 0; c < nch; c++) {
        if (c + 1 < nch) {
            gemm2_load_stage(sb + ((c + 1) & 1) * STAGE_B, m0, (c + 1) << 5, M);
            CP_COMMIT;
            CP_WAIT(1);
        } else {
            CP_WAIT(0);
        }
        __syncthreads();
        uint32_t stg = sb + (c & 1) * STAGE_B;
        compute_chunk(stg, stg + TILE_B, stg + 2 * TILE_B, stg + 3 * TILE_B,
                      warp_m, warp_n, lane, acc);
        __syncthreads();
    }
    gemm_epilogue_f32(acc, m0, warp_m, warp_n, lane, M);
}

// ============ classifier: bf16 HMMA, BM=128 BN=64(40) ∥ zero g_deg ===========
#define CTILE_A (128 * SKEW * 2)
#define CTILE_Bc (64 * SKEW * 2)
#define CSTAGE (2 * CTILE_A + 2 * CTILE_Bc)
#define CSM_TOTAL (2 * CSTAGE)

__device__ __forceinline__ void clf_load_stage(uint32_t sbase, int m0, int kc, int M) {
    int tid = threadIdx.x;
    #pragma unroll
    for (int it = 0; it < 2; it++) {
        int id = it * 256 + tid;
        int row = id >> 2, seg = id & 3;
        uint32_t soff = (uint32_t)(row * SKEW + seg * 8) * 2;
        int gr = m0 + row;
        int ok = (gr < M) ? 16 : 0;
        size_t grc = (gr < M) ? (size_t)gr : 0;
        CP_ASYNC16(sbase + soff,           g_Ahi + grc * FH + kc + seg * 8, ok);
        CP_ASYNC16(sbase + CTILE_A + soff, g_Alo + grc * FH + kc + seg * 8, ok);
    }
    {
        int row = tid >> 2, seg = tid & 3;
        uint32_t soff = (uint32_t)(row * SKEW + seg * 8) * 2;
        CP_ASYNC16(sbase + 2 * CTILE_A + soff,            g_Wcthi + (size_t)row * FH + kc + seg * 8, 16);
        CP_ASYNC16(sbase + 2 * CTILE_A + CTILE_Bc + soff, g_Wctlo + (size_t)row * FH + kc + seg * 8, 16);
    }
}

__global__ void __launch_bounds__(256, 2) mma_clf(const float* __restrict__ bias,
                                                  float* __restrict__ out, int M, int gemmB) {
    extern __shared__ char smem[];
    if (blockIdx.x >= gemmB) {
        // zero g_deg for the next graph replay (deg rebuilt from 0 each run)
        int i = (blockIdx.x - gemmB) * 256 + threadIdx.x;
        if (i < NN) g_deg[i] = 0;
        return;
    }
    uint32_t sb = smem_u32(smem);
    int tid = threadIdx.x, wid = tid >> 5, lane = tid & 31;
    int m0 = blockIdx.x * 128;
    int warp_m = wid & 3, warp_n = wid >> 2;

    float acc[2][4][4] = {};
    const int nch = FH >> 5;

    clf_load_stage(sb, m0, 0, M);
    CP_COMMIT;
    for (int c = 0; c < nch; c++) {
        if (c + 1 < nch) {
            clf_load_stage(sb + ((c + 1) & 1) * CSTAGE, m0, (c + 1) << 5, M);
            CP_COMMIT;
            CP_WAIT(1);
        } else {
            CP_WAIT(0);
        }
        __syncthreads();

        uint32_t stg = sb + (c & 1) * CSTAGE;
        uint32_t aAhi = stg, aAlo = stg + CTILE_A;
        uint32_t aBhi = stg + 2 * CTILE_A, aBlo = aBhi + CTILE_Bc;

        #pragma unroll
        for (int kk = 0; kk < 32; kk += 16) {
            uint32_t ah[2][4], al[2][4];
            #pragma unroll
            for (int mi = 0; mi < 2; mi++) {
                int row = warp_m * 32 + mi * 16 + (lane & 15);
                int col = kk + (lane >> 4) * 8;
                uint32_t off = (uint32_t)(row * SKEW + col) * 2;
                LDSM_X4(ah[mi][0], ah[mi][1], ah[mi][2], ah[mi][3], aAhi + off);
                LDSM_X4(al[mi][0], al[mi][1], al[mi][2], al[mi][3], aAlo + off);
            }
            uint32_t b[4][2];
            int g = lane >> 3;
            #pragma unroll
            for (int p = 0; p < 2; p++) {
                int nrow = warp_n * 32 + p * 16 + (g >> 1) * 8 + (lane & 7);
                int col = kk + (g & 1) * 8;
                uint32_t off = (uint32_t)(nrow * SKEW + col) * 2;
                uint32_t r0, r1, r2, r3;
                LDSM_X4(r0, r1, r2, r3, aBhi + off);
                b[p * 2][0] = r0; b[p * 2][1] = r1;
                b[p * 2 + 1][0] = r2; b[p * 2 + 1][1] = r3;
            }
            #pragma unroll
            for (int mi = 0; mi < 2; mi++)
                #pragma unroll
                for (int ni = 0; ni < 4; ni++) {
                    MMA16816(acc[mi][ni], ah[mi], b[ni]);
                    MMA16816(acc[mi][ni], al[mi], b[ni]);
                }
            #pragma unroll
            for (int p = 0; p < 2; p++) {
                int nrow = warp_n * 32 + p * 16 + (g >> 1) * 8 + (lane & 7);
                int col = kk + (g & 1) * 8;
                uint32_t off = (uint32_t)(nrow * SKEW + col) * 2;
                uint32_t r0, r1, r2, r3;
                LDSM_X4(r0, r1, r2, r3, aBlo + off);
                b[p * 2][0] = r0; b[p * 2][1] = r1;
                b[p * 2 + 1][0] = r2; b[p * 2 + 1][1] = r3;
            }
            #pragma unroll
            for (int mi = 0; mi < 2; mi++)
                #pragma unroll
                for (int ni = 0; ni < 4; ni++)
                    MMA16816(acc[mi][ni], ah[mi], b[ni]);
        }
        __syncthreads();
    }

    int gid = lane >> 2, tig = lane & 3;
    #pragma unroll
    for (int mi = 0; mi < 2; mi++) {
        #pragma unroll
        for (int ni = 0; ni < 4; ni++) {
            int col = warp_n * 32 + ni * 8 + tig * 2;
            if (col >= FC) continue;
            float b0 = bias[col], b1 = bias[col + 1];
            int r0 = m0 + warp_m * 32 + mi * 16 + gid;
            if (r0 < M)
                *(float2*)(out + (size_t)r0 * FC + col) =
                    make_float2(acc[mi][ni][0] + b0, acc[mi][ni][1] + b1);
            int r1 = r0 + 8;
            if (r1 < M)
                *(float2*)(out + (size_t)r1 * FC + col) =
                    make_float2(acc[mi][ni][2] + b0, acc[mi][ni][3] + b1);
        }
    }
}

// ---------------- launch ----------------
extern "C" void kernel_launch(void* const* d_in, const int* in_sizes, int n_in,
                              void* d_out, int out_size) {
    const float* x  = (const float*)d_in[0];
    const void*  ei = d_in[1];
    const float* W1 = (const float*)d_in[2];
    const float* b1 = (const float*)d_in[3];
    const float* W2 = (const float*)d_in[4];
    const float* b2 = (const float*)d_in[5];
    const float* Wc = (const float*)d_in[6];
    const float* bc = (const float*)d_in[7];
    float*       out = (float*)d_out;

    const int n = in_sizes[0] / F0;   // 100000
    const int E = in_sizes[1] / 2;    // 1600000

    cudaFuncSetAttribute(k2_gemm1_deg, cudaFuncAttributeMaxDynamicSharedMemorySize, GSM_TOTAL);
    cudaFuncSetAttribute(mma_gemm2, cudaFuncAttributeMaxDynamicSharedMemorySize, GSM_TOTAL);
    cudaFuncSetAttribute(mma_clf, cudaFuncAttributeMaxDynamicSharedMemorySize, CSM_TOTAL);

    int zB    = (n + 255) / 256;              // 391
    int bW1   = (F0 * FH + 255) / 256;        // 128
    int bW2   = (FH * FH + 255) / 256;        // 64
    int bWc   = (64 * FH + 255) / 256;        // 32
    int gemmB = (n + 127) / 128;              // 782
    int degB  = (E + 1023) / 1024;            // 1563
    int scatB = (E + 2047) / 2048;            // 782
    int dinvB = (n + 255) / 256;              // 391

    // K0: detect ∥ weight splits (deg zeroed at end of previous replay)
    k0_prep<<<1 + bW1 + bW2 + bWc, 256>>>((const int*)ei, 2 * E, W1, W2, Wc, bW1, bW2);
    // K2: gemm1 (fp16 out) ∥ degree histogram
    k2_gemm1_deg<<<gemmB + degB, 256, GSM_TOTAL>>>(x, ei, n, E, gemmB);
    // scan (tiny)
    scan_kernel<<<1, 1024>>>(n);
    // K3: scatter ∥ dinv
    k3_scatter_dinv<<<scatB + dinvB, 256>>>(ei, E, n, scatB);
    // agg1: gather fp16
    agg_kernel<<<(n + 7) / 8, 256>>>(b1, n, 1);
    // gemm2 (fp32 out)
    mma_gemm2<<<gemmB, 256, GSM_TOTAL>>>(n);
    // agg2: gather fp32
    agg_kernel<<<(n + 7) / 8, 256>>>(b2, n, 0);
    // classifier ∥ zero g_deg for next replay
    mma_clf<<<gemmB + zB, 256, CSM_TOTAL>>>(bc, out, n, gemmB);
}

// round 16
// speedup vs baseline: 1.2683x; 1.2683x over previous
#include <cuda_runtime.h>
#include <cuda_bf16.h>
#include <cuda_fp16.h>
#include <cstdint>

#define NN 100000
#define EE 1600000
#define F0 256
#define FH 128
#define FC 40

// ---------------- static device scratch ----------------
__device__ __half g_hh[(size_t)NN * FH];   // gemm outputs (fp16), read by agg
__device__ __half g_ah[(size_t)NN * FH];   // agg outputs (fp16), GEMM A operand
__device__ int   g_deg[NN];
__device__ float g_dinv[NN];
__device__ int   g_rowptr[NN + 1];
__device__ int   g_col[EE];
__device__ int   g_slot[EE];
__device__ int   g_is64;
__device__ __half g_W1t[FH * F0];          // [128][256] K-major fp16
__device__ __half g_W2t[FH * FH];          // [128][128] K-major fp16
__device__ __half g_Wct[64 * FH];          // [64(pad40)][128] K-major fp16

// ---------------- helpers ----------------
__device__ __forceinline__ uint32_t smem_u32(const void* p) {
    uint32_t a;
    asm("{ .reg .u64 t; cvta.to.shared.u64 t, %1; cvt.u32.u64 %0, t; }" : "=r"(a) : "l"(p));
    return a;
}
#define LDSM_X4(r0, r1, r2, r3, addr) \
    asm volatile("ldmatrix.sync.aligned.m8n8.x4.shared.b16 {%0,%1,%2,%3}, [%4];" \
                 : "=r"(r0), "=r"(r1), "=r"(r2), "=r"(r3) : "r"(addr))
#define MMA16816H(d, a, b) \
    asm volatile("mma.sync.aligned.m16n8k16.row.col.f32.f16.f16.f32 " \
                 "{%0,%1,%2,%3}, {%4,%5,%6,%7}, {%8,%9}, {%0,%1,%2,%3};" \
                 : "+f"((d)[0]), "+f"((d)[1]), "+f"((d)[2]), "+f"((d)[3]) \
                 : "r"((a)[0]), "r"((a)[1]), "r"((a)[2]), "r"((a)[3]), \
                   "r"((b)[0]), "r"((b)[1]))
#define CP_ASYNC16(dst, src, sz) \
    asm volatile("cp.async.cg.shared.global [%0], [%1], 16, %2;" \
                 :: "r"(dst), "l"(src), "r"(sz) : "memory")
#define CP_COMMIT asm volatile("cp.async.commit_group;" ::: "memory")
#define CP_WAIT(n) asm volatile("cp.async.wait_group %0;" :: "n"(n) : "memory")

__device__ __forceinline__ int load_edge(const void* ei, long long idx, int is64) {
    if (is64) return (int)((const long long*)ei)[idx];
    return ((const int*)ei)[idx];
}

#define SKEW 40
#define TILE_B (128 * SKEW * 2)     // 10240 bytes (128 rows x 40 halves)
#define BCT (64 * SKEW * 2)         // 5120 (64-row B tile for clf)
#define G1_SM (3 * TILE_B)          // gemm1: A single + B double = 30720
#define G2_SM (4 * TILE_B)          // gemm2: (A+B) double      = 40960
#define CSTAGE (TILE_B + BCT)       // clf stage = 15360
#define CL_SM (2 * CSTAGE)          // 30720

// ============ K0: detect ∥ convert W1/W2/Wc to fp16 ==========================
__global__ void k0_prep(const int* __restrict__ ei32, int total_words,
                        const float* __restrict__ W1, const float* __restrict__ W2,
                        const float* __restrict__ Wc, int bW1, int bW2) {
    int b = blockIdx.x, tid = threadIdx.x;
    if (b == 0) {
        __shared__ int acc;
        if (tid == 0) acc = 0;
        __syncthreads();
        int v = 0;
        int lim = min(total_words, 8192);
        for (int i = 1 + 2 * tid; i < lim; i += 2 * blockDim.x) v |= ei32[i];
        if (v) atomicOr(&acc, 1);
        __syncthreads();
        if (tid == 0) g_is64 = (acc == 0) ? 1 : 0;
    } else if (b < 1 + bW1) {
        int i = (b - 1) * 256 + tid;
        if (i < F0 * FH) {
            int k = i / FH, nidx = i % FH;
            g_W1t[nidx * F0 + k] = __float2half(W1[i]);
        }
    } else if (b < 1 + bW1 + bW2) {
        int i = (b - 1 - bW1) * 256 + tid;
        if (i < FH * FH) {
            int k = i / FH, nidx = i % FH;
            g_W2t[nidx * FH + k] = __float2half(W2[i]);
        }
    } else {
        int i = (b - 1 - bW1 - bW2) * 256 + tid;
        if (i < 64 * FH) {
            int nidx = i / FH, k = i % FH;
            float f = (nidx < FC) ? Wc[k * FC + nidx] : 0.f;
            g_Wct[nidx * FH + k] = __float2half(f);
        }
    }
}

// ============ scan: exclusive prefix of g_deg -> g_rowptr (1 block) ==========
__global__ void scan_kernel(int n) {
    __shared__ int sh[1024];
    int tid = threadIdx.x;
    int chunk = (n + 1023) >> 10;
    int start = tid * chunk, end = min(start + chunk, n);
    int sum = 0;
    for (int i = start; i < end; i++) sum += g_deg[i];
    sh[tid] = sum;
    __syncthreads();
    for (int off = 1; off < 1024; off <<= 1) {
        int v = 0;
        if (tid >= off) v = sh[tid - off];
        __syncthreads();
        sh[tid] += v;
        __syncthreads();
    }
    int run = sh[tid] - sum;
    for (int i = start; i < end; i++) { g_rowptr[i] = run; run += g_deg[i]; }
    if (end == n) g_rowptr[n] = run;
}

// ============ single-term fp16 MMA for one 32-wide K chunk (BN=128) ==========
__device__ __forceinline__ void compute_chunk1(
    uint32_t aA, uint32_t aB, int warp_m, int warp_n, int lane, float acc[2][8][4])
{
    #pragma unroll
    for (int kk = 0; kk < 32; kk += 16) {
        uint32_t a[2][4];
        #pragma unroll
        for (int mi = 0; mi < 2; mi++) {
            int row = warp_m * 32 + mi * 16 + (lane & 15);
            int col = kk + (lane >> 4) * 8;
            uint32_t off = (uint32_t)(row * SKEW + col) * 2;
            LDSM_X4(a[mi][0], a[mi][1], a[mi][2], a[mi][3], aA + off);
        }
        uint32_t b[8][2];
        int g = lane >> 3;
        #pragma unroll
        for (int p = 0; p < 4; p++) {
            int nrow = warp_n * 64 + p * 16 + (g >> 1) * 8 + (lane & 7);
            int col = kk + (g & 1) * 8;
            uint32_t off = (uint32_t)(nrow * SKEW + col) * 2;
            uint32_t r0, r1, r2, r3;
            LDSM_X4(r0, r1, r2, r3, aB + off);
            b[p * 2][0] = r0; b[p * 2][1] = r1;
            b[p * 2 + 1][0] = r2; b[p * 2 + 1][1] = r3;
        }
        #pragma unroll
        for (int mi = 0; mi < 2; mi++)
            #pragma unroll
            for (int ni = 0; ni < 8; ni++)
                MMA16816H(acc[mi][ni], a[mi], b[ni]);
    }
}

// fp16 epilogue -> g_hh
__device__ __forceinline__ void gemm_epilogue_f16(float acc[2][8][4], int m0,
                                                  int warp_m, int warp_n, int lane, int M) {
    int gid = lane >> 2, tig = lane & 3;
    #pragma unroll
    for (int mi = 0; mi < 2; mi++) {
        #pragma unroll
        for (int ni = 0; ni < 8; ni++) {
            int col = warp_n * 64 + ni * 8 + tig * 2;
            int r0 = m0 + warp_m * 32 + mi * 16 + gid;
            if (r0 < M)
                *(__half2*)(g_hh + (size_t)r0 * 128 + col) =
                    __floats2half2_rn(acc[mi][ni][0], acc[mi][ni][1]);
            int r1 = r0 + 8;
            if (r1 < M)
                *(__half2*)(g_hh + (size_t)r1 * 128 + col) =
                    __floats2half2_rn(acc[mi][ni][2], acc[mi][ni][3]);
        }
    }
}

// ============ GEMM-1: x fp32 -> fp16 on the fly; B fp16 double-buffered ======
__device__ void mma_gemm1_dev(char* smem, int bidx, const float* __restrict__ x, int M) {
    uint32_t sb = smem_u32(smem);
    int tid = threadIdx.x, wid = tid >> 5, lane = tid & 31;
    int m0 = bidx * 128;
    int warp_m = wid & 3, warp_n = wid >> 2;
    const int K = F0, nch = K >> 5;   // 8

    float acc[2][8][4] = {};
    float4 f[4];

    #define L1_LOADB(c) do { \
        uint32_t base = sb + TILE_B + ((c) & 1) * TILE_B; \
        _Pragma("unroll") \
        for (int it = 0; it < 2; it++) { \
            int id = it * 256 + tid; \
            int row = id >> 2, seg = id & 3; \
            uint32_t soff = (uint32_t)(row * SKEW + seg * 8) * 2; \
            CP_ASYNC16(base + soff, g_W1t + (size_t)row * K + ((c) << 5) + seg * 8, 16); \
        } \
        CP_COMMIT; \
    } while (0)
    #define L1_LOADA(c) do { \
        _Pragma("unroll") \
        for (int it = 0; it < 4; it++) { \
            int id = it * 256 + tid; \
            int row = id >> 3, seg = id & 7; \
            int gr = m0 + row; \
            f[it] = (gr < M) ? *(const float4*)(x + (size_t)gr * K + ((c) << 5) + seg * 4) \
                             : make_float4(0.f, 0.f, 0.f, 0.f); \
        } \
    } while (0)

    L1_LOADB(0);
    L1_LOADA(0);

    for (int c = 0; c < nch; c++) {
        __syncthreads();   // prior reads of A smem & B[(c+1)&1] complete
        if (c + 1 < nch) L1_LOADB(c + 1);
        #pragma unroll
        for (int it = 0; it < 4; it++) {
            int id = it * 256 + tid;
            int row = id >> 3, seg = id & 7;
            __half2 p0 = __floats2half2_rn(f[it].x, f[it].y);
            __half2 p1 = __floats2half2_rn(f[it].z, f[it].w);
            uint32_t soff = (uint32_t)(row * SKEW + seg * 4) * 2;
            *(uint2*)(smem + soff) = make_uint2(*(uint32_t*)&p0, *(uint32_t*)&p1);
        }
        if (c + 1 < nch) { L1_LOADA(c + 1); CP_WAIT(1); }
        else             { CP_WAIT(0); }
        __syncthreads();

        compute_chunk1(sb, sb + TILE_B + (c & 1) * TILE_B, warp_m, warp_n, lane, acc);
    }
    gemm_epilogue_f16(acc, m0, warp_m, warp_n, lane, M);
    #undef L1_LOADB
    #undef L1_LOADA
}

// ============ K2: GEMM-1 ∥ degree histogram ==================================
__global__ void __launch_bounds__(256, 2) k2_gemm1_deg(
    const float* __restrict__ x, const void* __restrict__ ei, int M, int E, int gemmB) {
    extern __shared__ char smem[];
    if (blockIdx.x < gemmB) {
        mma_gemm1_dev(smem, blockIdx.x, x, M);
    } else {
        int is64 = g_is64;
        int base = ((blockIdx.x - gemmB) * 256 + threadIdx.x) * 4;
        #pragma unroll
        for (int j = 0; j < 4; j++) {
            int i = base + j;
            if (i >= E) break;
            int d = load_edge(ei, (long long)E + i, is64);
            if ((unsigned)d < (unsigned)NN)
                g_slot[i] = atomicAdd(&g_deg[d], 1);
        }
    }
}

// ============ K3: scatter (col only) ∥ dinv ==================================
__global__ void k3_scatter_dinv(const void* __restrict__ ei, int E, int n, int scatB) {
    if (blockIdx.x < scatB) {
        int is64 = g_is64;
        int base = (blockIdx.x * 256 + threadIdx.x) * 8;
        #pragma unroll
        for (int j = 0; j < 8; j++) {
            int i = base + j;
            if (i >= E) break;
            int s = load_edge(ei, i, is64);
            int d = load_edge(ei, (long long)E + i, is64);
            if ((unsigned)s >= (unsigned)NN || (unsigned)d >= (unsigned)NN) continue;
            g_col[g_rowptr[d] + g_slot[i]] = s;
        }
    } else {
        int i = (blockIdx.x - scatB) * 256 + threadIdx.x;
        if (i < n) g_dinv[i] = rsqrtf((float)g_deg[i] + 1.0f);
    }
}

// ---------------- aggregation: warp/node, 4-way ILP, fp16 in/out -------------
// g_ah[i] = fp16( relu( di·Σ dinv[s]·g_hh[s] + di²·g_hh[i] + bias ) )
__global__ void agg_kernel(const float* __restrict__ bias, int n) {
    int warp = (blockIdx.x * blockDim.x + threadIdx.x) >> 5;
    if (warp >= n) return;
    int lane = threadIdx.x & 31;
    int beg = g_rowptr[warp], end = g_rowptr[warp + 1];
    const uint2* hh = (const uint2*)g_hh;   // 4 halves per lane-slot

    float4 a0 = make_float4(0.f, 0.f, 0.f, 0.f), a1 = a0, a2 = a0, a3 = a0;
    int e = beg;
    for (; e + 4 <= end; e += 4) {
        int s0 = g_col[e],     s1 = g_col[e + 1];
        int s2 = g_col[e + 2], s3 = g_col[e + 3];
        float w0 = g_dinv[s0], w1 = g_dinv[s1];
        float w2 = g_dinv[s2], w3 = g_dinv[s3];
        uint2 r0 = hh[(size_t)s0 * 32 + lane];
        uint2 r1 = hh[(size_t)s1 * 32 + lane];
        uint2 r2 = hh[(size_t)s2 * 32 + lane];
        uint2 r3 = hh[(size_t)s3 * 32 + lane];
        float2 p0 = __half22float2(*(__half2*)&r0.x), q0 = __half22float2(*(__half2*)&r0.y);
        float2 p1 = __half22float2(*(__half2*)&r1.x), q1 = __half22float2(*(__half2*)&r1.y);
        float2 p2 = __half22float2(*(__half2*)&r2.x), q2 = __half22float2(*(__half2*)&r2.y);
        float2 p3 = __half22float2(*(__half2*)&r3.x), q3 = __half22float2(*(__half2*)&r3.y);
        a0.x += w0 * p0.x; a0.y += w0 * p0.y; a0.z += w0 * q0.x; a0.w += w0 * q0.y;
        a1.x += w1 * p1.x; a1.y += w1 * p1.y; a1.z += w1 * q1.x; a1.w += w1 * q1.y;
        a2.x += w2 * p2.x; a2.y += w2 * p2.y; a2.z += w2 * q2.x; a2.w += w2 * q2.y;
        a3.x += w3 * p3.x; a3.y += w3 * p3.y; a3.z += w3 * q3.x; a3.w += w3 * q3.y;
    }
    for (; e < end; e++) {
        int s0 = g_col[e];
        float w0 = g_dinv[s0];
        uint2 r0 = hh[(size_t)s0 * 32 + lane];
        float2 p0 = __half22float2(*(__half2*)&r0.x), q0 = __half22float2(*(__half2*)&r0.y);
        a0.x += w0 * p0.x; a0.y += w0 * p0.y; a0.z += w0 * q0.x; a0.w += w0 * q0.y;
    }
    a0.x += a1.x + a2.x + a3.x;
    a0.y += a1.y + a2.y + a3.y;
    a0.z += a1.z + a2.z + a3.z;
    a0.w += a1.w + a2.w + a3.w;

    float di = g_dinv[warp], di2 = di * di;
    uint2 rs = hh[(size_t)warp * 32 + lane];
    float2 ps = __half22float2(*(__half2*)&rs.x), qs = __half22float2(*(__half2*)&rs.y);
    float4 bb = ((const float4*)bias)[lane];
    float4 r;
    r.x = fmaxf(di * a0.x + di2 * ps.x + bb.x, 0.f);
    r.y = fmaxf(di * a0.y + di2 * ps.y + bb.y, 0.f);
    r.z = fmaxf(di * a0.z + di2 * qs.x + bb.z, 0.f);
    r.w = fmaxf(di * a0.w + di2 * qs.y + bb.w, 0.f);

    __half2 o0 = __floats2half2_rn(r.x, r.y);
    __half2 o1 = __floats2half2_rn(r.z, r.w);
    *(uint2*)(g_ah + (size_t)warp * 128 + lane * 4) =
        make_uint2(*(uint32_t*)&o0, *(uint32_t*)&o1);
}

// ============ GEMM-2: A fp16 from g_ah, B fp16 (cp.async 2-stage) ============
__device__ __forceinline__ void gemm2_load_stage(uint32_t sbase, int m0, int kc, int M) {
    int tid = threadIdx.x;
    #pragma unroll
    for (int it = 0; it < 2; it++) {
        int id = it * 256 + tid;
        int row = id >> 2, seg = id & 3;
        uint32_t soff = (uint32_t)(row * SKEW + seg * 8) * 2;
        int gr = m0 + row;
        int ok = (gr < M) ? 16 : 0;
        size_t grc = (gr < M) ? (size_t)gr : 0;
        CP_ASYNC16(sbase + soff,          g_ah + grc * FH + kc + seg * 8, ok);
        CP_ASYNC16(sbase + TILE_B + soff, g_W2t + (size_t)row * FH + kc + seg * 8, 16);
    }
}

__global__ void __launch_bounds__(256, 2) mma_gemm2(int M) {
    extern __shared__ char smem[];
    uint32_t sb = smem_u32(smem);
    int tid = threadIdx.x, wid = tid >> 5, lane = tid & 31;
    int m0 = blockIdx.x * 128;
    int warp_m = wid & 3, warp_n = wid >> 2;

    float acc[2][8][4] = {};
    const int nch = FH >> 5;   // 4

    gemm2_load_stage(sb, m0, 0, M);
    CP_COMMIT;
    for (int c = 0; c < nch; c++) {
        if (c + 1 < nch) {
            gemm2_load_stage(sb + ((c + 1) & 1) * (2 * TILE_B), m0, (c + 1) << 5, M);
            CP_COMMIT;
            CP_WAIT(1);
        } else {
            CP_WAIT(0);
        }
        __syncthreads();
        uint32_t stg = sb + (c & 1) * (2 * TILE_B);
        compute_chunk1(stg, stg + TILE_B, warp_m, warp_n, lane, acc);
        __syncthreads();
    }
    gemm_epilogue_f16(acc, m0, warp_m, warp_n, lane, M);
}

// ============ classifier: fp16 HMMA, BM=128 BN=64(40) ∥ zero g_deg ===========
__device__ __forceinline__ void clf_load_stage(uint32_t sbase, int m0, int kc, int M) {
    int tid = threadIdx.x;
    #pragma unroll
    for (int it = 0; it < 2; it++) {
        int id = it * 256 + tid;
        int row = id >> 2, seg = id & 3;
        uint32_t soff = (uint32_t)(row * SKEW + seg * 8) * 2;
        int gr = m0 + row;
        int ok = (gr < M) ? 16 : 0;
        size_t grc = (gr < M) ? (size_t)gr : 0;
        CP_ASYNC16(sbase + soff, g_ah + grc * FH + kc + seg * 8, ok);
    }
    {
        int row = tid >> 2, seg = tid & 3;
        if (row < 64) {
            uint32_t soff = (uint32_t)(row * SKEW + seg * 8) * 2;
            CP_ASYNC16(sbase + TILE_B + soff, g_Wct + (size_t)row * FH + kc + seg * 8, 16);
        }
    }
}

__global__ void __launch_bounds__(256, 2) mma_clf(const float* __restrict__ bias,
                                                  float* __restrict__ out, int M, int gemmB) {
    extern __shared__ char smem[];
    if (blockIdx.x >= gemmB) {
        int i = (blockIdx.x - gemmB) * 256 + threadIdx.x;
        if (i < NN) g_deg[i] = 0;   // zero for next replay (rebuilt each run)
        return;
    }
    uint32_t sb = smem_u32(smem);
    int tid = threadIdx.x, wid = tid >> 5, lane = tid & 31;
    int m0 = blockIdx.x * 128;
    int warp_m = wid & 3, warp_n = wid >> 2;   // warp tile 32x32 over N=64

    float acc[2][4][4] = {};
    const int nch = FH >> 5;

    clf_load_stage(sb, m0, 0, M);
    CP_COMMIT;
    for (int c = 0; c < nch; c++) {
        if (c + 1 < nch) {
            clf_load_stage(sb + ((c + 1) & 1) * CSTAGE, m0, (c + 1) << 5, M);
            CP_COMMIT;
            CP_WAIT(1);
        } else {
            CP_WAIT(0);
        }
        __syncthreads();

        uint32_t aA = sb + (c & 1) * CSTAGE;
        uint32_t aB = aA + TILE_B;

        #pragma unroll
        for (int kk = 0; kk < 32; kk += 16) {
            uint32_t a[2][4];
            #pragma unroll
            for (int mi = 0; mi < 2; mi++) {
                int row = warp_m * 32 + mi * 16 + (lane & 15);
                int col = kk + (lane >> 4) * 8;
                uint32_t off = (uint32_t)(row * SKEW + col) * 2;
                LDSM_X4(a[mi][0], a[mi][1], a[mi][2], a[mi][3], aA + off);
            }
            uint32_t b[4][2];
            int g = lane >> 3;
            #pragma unroll
            for (int p = 0; p < 2; p++) {
                int nrow = warp_n * 32 + p * 16 + (g >> 1) * 8 + (lane & 7);
                int col = kk + (g & 1) * 8;
                uint32_t off = (uint32_t)(nrow * SKEW + col) * 2;
                uint32_t r0, r1, r2, r3;
                LDSM_X4(r0, r1, r2, r3, aB + off);
                b[p * 2][0] = r0; b[p * 2][1] = r1;
                b[p * 2 + 1][0] = r2; b[p * 2 + 1][1] = r3;
            }
            #pragma unroll
            for (int mi = 0; mi < 2; mi++)
                #pragma unroll
                for (int ni = 0; ni < 4; ni++)
                    MMA16816H(acc[mi][ni], a[mi], b[ni]);
        }
        __syncthreads();
    }

    int gid = lane >> 2, tig = lane & 3;
    #pragma unroll
    for (int mi = 0; mi < 2; mi++) {
        #pragma unroll
        for (int ni = 0; ni < 4; ni++) {
            int col = warp_n * 32 + ni * 8 + tig * 2;
            if (col >= FC) continue;
            float b0 = bias[col], b1 = bias[col + 1];
            int r0 = m0 + warp_m * 32 + mi * 16 + gid;
            if (r0 < M)
                *(float2*)(out + (size_t)r0 * FC + col) =
                    make_float2(acc[mi][ni][0] + b0, acc[mi][ni][1] + b1);
            int r1 = r0 + 8;
            if (r1 < M)
                *(float2*)(out + (size_t)r1 * FC + col) =
                    make_float2(acc[mi][ni][2] + b0, acc[mi][ni][3] + b1);
        }
    }
}

// ---------------- launch ----------------
extern "C" void kernel_launch(void* const* d_in, const int* in_sizes, int n_in,
                              void* d_out, int out_size) {
    const float* x  = (const float*)d_in[0];
    const void*  ei = d_in[1];
    const float* W1 = (const float*)d_in[2];
    const float* b1 = (const float*)d_in[3];
    const float* W2 = (const float*)d_in[4];
    const float* b2 = (const float*)d_in[5];
    const float* Wc = (const float*)d_in[6];
    const float* bc = (const float*)d_in[7];
    float*       out = (float*)d_out;

    const int n = in_sizes[0] / F0;   // 100000
    const int E = in_sizes[1] / 2;    // 1600000

    cudaFuncSetAttribute(k2_gemm1_deg, cudaFuncAttributeMaxDynamicSharedMemorySize, G1_SM);
    cudaFuncSetAttribute(mma_gemm2, cudaFuncAttributeMaxDynamicSharedMemorySize, G2_SM);
    cudaFuncSetAttribute(mma_clf, cudaFuncAttributeMaxDynamicSharedMemorySize, CL_SM);

    int zB    = (n + 255) / 256;              // 391
    int bW1   = (F0 * FH + 255) / 256;        // 128
    int bW2   = (FH * FH + 255) / 256;        // 64
    int bWc   = (64 * FH + 255) / 256;        // 32
    int gemmB = (n + 127) / 128;              // 782
    int degB  = (E + 1023) / 1024;            // 1563
    int scatB = (E + 2047) / 2048;            // 782
    int dinvB = (n + 255) / 256;              // 391

    // K0: detect ∥ weight fp16 conversion (deg zeroed at end of prev replay)
    k0_prep<<<1 + bW1 + bW2 + bWc, 256>>>((const int*)ei, 2 * E, W1, W2, Wc, bW1, bW2);
    // K2: gemm1 (fp16) ∥ degree histogram
    k2_gemm1_deg<<<gemmB + degB, 256, G1_SM>>>(x, ei, n, E, gemmB);
    // scan
    scan_kernel<<<1, 1024>>>(n);
    // K3: scatter ∥ dinv
    k3_scatter_dinv<<<scatB + dinvB, 256>>>(ei, E, n, scatB);
    // agg1 (fp16 in/out)
    agg_kernel<<<(n + 7) / 8, 256>>>(b1, n);
    // gemm2 (fp16)
    mma_gemm2<<<gemmB, 256, G2_SM>>>(n);
    // agg2 (fp16 in/out)
    agg_kernel<<<(n + 7) / 8, 256>>>(b2, n);
    // classifier ∥ zero g_deg for next replay
    mma_clf<<<gemmB + zB, 256, CL_SM>>>(bc, out, n, gemmB);
}